// round 4
// baseline (speedup 1.0000x reference)
#include <cuda_runtime.h>

#define HID 64
#define MAX_NODES 100000
#define MAX_EDGES 2000000
#define TE 192                 // edges per tile (16 ty-groups x 12 edges)
#define EDGE_SMEM ((64 * TE + 64 * 64) * 4)      // sDT + sC = 65536 B
#define NODE_SMEM ((3 * 4096 + 64 * 65) * 4)     // sW2,sA,sB + padded h tile

typedef unsigned long long ull;

__device__ float g_H[MAX_NODES * HID];
__device__ float g_P[MAX_NODES * HID];
__device__ float g_Q[MAX_NODES * HID];
__device__ int   g_U[MAX_EDGES];
__device__ int   g_V[MAX_EDGES];
__device__ int   g_is64;

// ---- packed f32x2 helpers ---------------------------------------------------
__device__ __forceinline__ ull pack2(float x, float y) {
    ull r; asm("mov.b64 %0, {%1, %2};" : "=l"(r) : "f"(x), "f"(y)); return r;
}
__device__ __forceinline__ void unpack2(ull v, float& x, float& y) {
    asm("mov.b64 {%0, %1}, %2;" : "=f"(x), "=f"(y) : "l"(v));
}
__device__ __forceinline__ ull ffma2(ull a, ull b, ull c) {
    ull r; asm("fma.rn.f32x2 %0, %1, %2, %3;" : "=l"(r) : "l"(a), "l"(b), "l"(c));
    return r;
}

// ---------------------------------------------------------------------------
// detect int64 vs int32 pairs (reads only first 2*n_edges words, in-bounds
// for both dtypes; int64 -> odd words all zero).
// ---------------------------------------------------------------------------
__global__ void detect_kernel(const int* __restrict__ w, int n_edges) {
    __shared__ int any_nz;
    if (threadIdx.x == 0) any_nz = 0;
    __syncthreads();
    int nz = 0;
    for (int j = threadIdx.x; j < 4096; j += blockDim.x) {
        long long idx = 1 + 2 * ((long long)j * (n_edges - 1) / 4096);
        if (idx < 2LL * n_edges) nz |= w[idx];
    }
    if (nz) atomicOr(&any_nz, 1);
    __syncthreads();
    if (threadIdx.x == 0) g_is64 = (any_nz == 0) ? 1 : 0;
}

__global__ void decode_kernel(const int* __restrict__ w, int n_edges) {
    int is64 = g_is64;
    int e = blockIdx.x * blockDim.x + threadIdx.x;
    if (e >= n_edges) return;
    int u, v;
    if (is64) { u = w[4LL * e]; v = w[4LL * e + 2]; }
    else      { u = w[2LL * e]; v = w[2LL * e + 1]; }
    g_U[e] = u;
    g_V[e] = v;
}

// ---------------------------------------------------------------------------
// Fused node kernel (persistent): per 64-node tile:
//   h1 = relu(X@W1+b1); H = relu(h1@W2+b2) -> g_H;
//   P = H@A + be1 -> g_P; Q = H@B -> g_Q.
// 256 thr = 16 q (dims 4q..4q+3) x 16 g (nodes 4g..4g+3). 4x4 register tile.
// h tile stored stride-65 (conflict-free scalar k-reads: bank = node+k).
// ---------------------------------------------------------------------------
__global__ __launch_bounds__(256) void node_kernel(
        const float* __restrict__ X,
        const float* __restrict__ W1, const float* __restrict__ b1,
        const float* __restrict__ W2, const float* __restrict__ b2,
        const float* __restrict__ We1, const float* __restrict__ be1,
        int n_nodes) {
    extern __shared__ float ns[];
    float* sW2 = ns;                 // [64][64]
    float* sA  = ns + 4096;          // [64][64]
    float* sB  = ns + 8192;          // [64][64]
    float* sh  = ns + 12288;         // [64][65] padded

    int tid = threadIdx.x;
    for (int i = tid; i < 4096; i += 256) {
        sW2[i] = W2[i];
        sA[i]  = We1[i];
        sB[i]  = We1[4096 + i];
    }

    int q = tid & 15;
    int g = tid >> 4;

    // hoisted per-thread constants
    float w1r[4][4];
    #pragma unroll
    for (int c = 0; c < 4; c++) {
        float4 w = *(const float4*)&W1[c * HID + 4 * q];
        w1r[c][0] = w.x; w1r[c][1] = w.y; w1r[c][2] = w.z; w1r[c][3] = w.w;
    }
    float4 b1r  = *(const float4*)&b1[4 * q];
    float4 b2r  = *(const float4*)&b2[4 * q];
    float4 be1r = *(const float4*)&be1[4 * q];
    __syncthreads();

    for (int base = blockIdx.x * 64; base < n_nodes; base += gridDim.x * 64) {
        // ---- phase 1: h1 = relu(X@W1+b1), store to sh (stride 65)
        #pragma unroll
        for (int i = 0; i < 4; i++) {
            int node = base + 4 * g + i;
            float4 x = (node < n_nodes) ? *(const float4*)&X[(size_t)node * 4]
                                        : make_float4(0.f, 0.f, 0.f, 0.f);
            #pragma unroll
            for (int m = 0; m < 4; m++) {
                float h = ((const float*)&b1r)[m];
                h = fmaf(x.x, w1r[0][m], h);
                h = fmaf(x.y, w1r[1][m], h);
                h = fmaf(x.z, w1r[2][m], h);
                h = fmaf(x.w, w1r[3][m], h);
                sh[(4 * g + i) * 65 + 4 * q + m] = fmaxf(h, 0.f);
            }
        }
        __syncthreads();

        // ---- phase 2: H = relu(h1@W2+b2)
        float acc[4][4];
        #pragma unroll
        for (int i = 0; i < 4; i++) {
            acc[i][0] = b2r.x; acc[i][1] = b2r.y;
            acc[i][2] = b2r.z; acc[i][3] = b2r.w;
        }
        #pragma unroll 8
        for (int k = 0; k < HID; k++) {
            float4 w = *(const float4*)&sW2[k * HID + 4 * q];
            #pragma unroll
            for (int i = 0; i < 4; i++) {
                float h = sh[(4 * g + i) * 65 + k];
                acc[i][0] = fmaf(h, w.x, acc[i][0]);
                acc[i][1] = fmaf(h, w.y, acc[i][1]);
                acc[i][2] = fmaf(h, w.z, acc[i][2]);
                acc[i][3] = fmaf(h, w.w, acc[i][3]);
            }
        }
        #pragma unroll
        for (int i = 0; i < 4; i++)
            #pragma unroll
            for (int m = 0; m < 4; m++)
                acc[i][m] = fmaxf(acc[i][m], 0.f);
        __syncthreads();     // all sh(h1) reads done

        // store H in-place into sh, and to gmem
        #pragma unroll
        for (int i = 0; i < 4; i++) {
            #pragma unroll
            for (int m = 0; m < 4; m++)
                sh[(4 * g + i) * 65 + 4 * q + m] = acc[i][m];
            int node = base + 4 * g + i;
            if (node < n_nodes)
                *(float4*)&g_H[(size_t)node * HID + 4 * q] =
                    make_float4(acc[i][0], acc[i][1], acc[i][2], acc[i][3]);
        }
        __syncthreads();

        // ---- phase 3: P = H@A + be1, Q = H@B
        float pacc[4][4], qacc[4][4];
        #pragma unroll
        for (int i = 0; i < 4; i++) {
            pacc[i][0] = be1r.x; pacc[i][1] = be1r.y;
            pacc[i][2] = be1r.z; pacc[i][3] = be1r.w;
            qacc[i][0] = qacc[i][1] = qacc[i][2] = qacc[i][3] = 0.f;
        }
        #pragma unroll 4
        for (int k = 0; k < HID; k++) {
            float4 a4 = *(const float4*)&sA[k * HID + 4 * q];
            float4 b4 = *(const float4*)&sB[k * HID + 4 * q];
            #pragma unroll
            for (int i = 0; i < 4; i++) {
                float h = sh[(4 * g + i) * 65 + k];
                pacc[i][0] = fmaf(h, a4.x, pacc[i][0]);
                pacc[i][1] = fmaf(h, a4.y, pacc[i][1]);
                pacc[i][2] = fmaf(h, a4.z, pacc[i][2]);
                pacc[i][3] = fmaf(h, a4.w, pacc[i][3]);
                qacc[i][0] = fmaf(h, b4.x, qacc[i][0]);
                qacc[i][1] = fmaf(h, b4.y, qacc[i][1]);
                qacc[i][2] = fmaf(h, b4.z, qacc[i][2]);
                qacc[i][3] = fmaf(h, b4.w, qacc[i][3]);
            }
        }
        #pragma unroll
        for (int i = 0; i < 4; i++) {
            int node = base + 4 * g + i;
            if (node < n_nodes) {
                *(float4*)&g_P[(size_t)node * HID + 4 * q] =
                    make_float4(pacc[i][0], pacc[i][1], pacc[i][2], pacc[i][3]);
                *(float4*)&g_Q[(size_t)node * HID + 4 * q] =
                    make_float4(qacc[i][0], qacc[i][1], qacc[i][2], qacc[i][3]);
            }
        }
        __syncthreads();     // before next iter's phase-1 sh stores
    }
}

// ---------------------------------------------------------------------------
// Edge kernel (persistent): tiles of TE=192 edges.
// 128 thr = 8 tx (dims 8tx..8tx+7, packed as 4 f32x2) x 16 ty (12 edges).
// Per k: 12 scalar d LDS + 12 splat movs (alu pipe) + 4 LDS.64 c + 48 FFMA2
// -> FMA2-bound (20 LDS-cyc vs 24 FMA-cyc per warp).
// ---------------------------------------------------------------------------
__global__ __launch_bounds__(128, 3) void edge_kernel(
        const float* __restrict__ We1,
        const float* __restrict__ We2,
        const float* __restrict__ be2,
        float* __restrict__ out,
        int n_edges) {
    extern __shared__ float es[];
    float* sDT = es;                // [64][TE] transposed diff tile
    float* sC  = es + 64 * TE;      // [64][64] natural

    __shared__ int su[TE], sv[TE];

    int tid = threadIdx.x;
    int tx  = tid & 7;
    int ty  = tid >> 3;

    const float* C = We1 + 2 * HID * HID;
    for (int i = tid; i < HID * HID; i += 128) sC[i] = C[i];

    // per-thread We2 slice + bias
    float w2r[8];
    {
        float4 wa = *(const float4*)&We2[8 * tx];
        float4 wb = *(const float4*)&We2[8 * tx + 4];
        w2r[0] = wa.x; w2r[1] = wa.y; w2r[2] = wa.z; w2r[3] = wa.w;
        w2r[4] = wb.x; w2r[5] = wb.y; w2r[6] = wb.z; w2r[7] = wb.w;
    }
    float bias = be2[0];

    int n_tiles = (n_edges + TE - 1) / TE;

    for (int tile = blockIdx.x; tile < n_tiles; tile += gridDim.x) {
        int e0 = tile * TE;

        __syncthreads();     // protect su/sv/sDT from previous tile
        for (int i = tid; i < TE; i += 128) {
            int e = e0 + i;
            su[i] = (e < n_edges) ? g_U[e] : 0;
            sv[i] = (e < n_edges) ? g_V[e] : 0;
        }
        __syncthreads();

        // fill transposed diff tile (1-2 edges per thread, coalesced STS)
        for (int e = tid; e < TE; e += 128) {
            const float4* Hu = (const float4*)&g_H[(size_t)su[e] * HID];
            const float4* Hv = (const float4*)&g_H[(size_t)sv[e] * HID];
            #pragma unroll
            for (int c = 0; c < 16; c++) {
                float4 a = Hu[c];
                float4 b = Hv[c];
                sDT[(4 * c + 0) * TE + e] = fabsf(a.x - b.x);
                sDT[(4 * c + 1) * TE + e] = fabsf(a.y - b.y);
                sDT[(4 * c + 2) * TE + e] = fabsf(a.z - b.z);
                sDT[(4 * c + 3) * TE + e] = fabsf(a.w - b.w);
            }
        }

        // acc init: P[u]+Q[v] (overlaps with fill LDGs above; sync below)
        ull acc[12][4];
        #pragma unroll
        for (int i = 0; i < 12; i++) {
            int e = 12 * ty + i;
            const float* Pu = &g_P[(size_t)su[e] * HID + 8 * tx];
            const float* Qv = &g_Q[(size_t)sv[e] * HID + 8 * tx];
            float4 p0 = *(const float4*)&Pu[0];
            float4 p1 = *(const float4*)&Pu[4];
            float4 q0 = *(const float4*)&Qv[0];
            float4 q1 = *(const float4*)&Qv[4];
            acc[i][0] = pack2(p0.x + q0.x, p0.y + q0.y);
            acc[i][1] = pack2(p0.z + q0.z, p0.w + q0.w);
            acc[i][2] = pack2(p1.x + q1.x, p1.y + q1.y);
            acc[i][3] = pack2(p1.z + q1.z, p1.w + q1.w);
        }
        __syncthreads();     // sDT ready

        // FFMA2 mainloop: acc[e][t-pair] += (d,d) * (c_t, c_t+1)
        const float* dB = sDT + 12 * ty;
        const ull*   cB = (const ull*)sC + 4 * tx;
        #pragma unroll 2
        for (int k = 0; k < HID; k++) {
            ull c0 = cB[k * 32 + 0];
            ull c1 = cB[k * 32 + 1];
            ull c2 = cB[k * 32 + 2];
            ull c3 = cB[k * 32 + 3];
            const float* dk = dB + k * TE;
            #pragma unroll
            for (int i = 0; i < 12; i++) {
                float d = dk[i];
                ull ds = pack2(d, d);
                acc[i][0] = ffma2(ds, c0, acc[i][0]);
                acc[i][1] = ffma2(ds, c1, acc[i][1]);
                acc[i][2] = ffma2(ds, c2, acc[i][2]);
                acc[i][3] = ffma2(ds, c3, acc[i][3]);
            }
        }

        // epilogue: relu, dot We2 slice, reduce over 8 tx lanes
        #pragma unroll
        for (int i = 0; i < 12; i++) {
            float x0, x1, s;
            unpack2(acc[i][0], x0, x1);
            s = fmaxf(x0, 0.f) * w2r[0];
            s = fmaf(fmaxf(x1, 0.f), w2r[1], s);
            unpack2(acc[i][1], x0, x1);
            s = fmaf(fmaxf(x0, 0.f), w2r[2], s);
            s = fmaf(fmaxf(x1, 0.f), w2r[3], s);
            unpack2(acc[i][2], x0, x1);
            s = fmaf(fmaxf(x0, 0.f), w2r[4], s);
            s = fmaf(fmaxf(x1, 0.f), w2r[5], s);
            unpack2(acc[i][3], x0, x1);
            s = fmaf(fmaxf(x0, 0.f), w2r[6], s);
            s = fmaf(fmaxf(x1, 0.f), w2r[7], s);
            s += __shfl_xor_sync(0xffffffffu, s, 1);
            s += __shfl_xor_sync(0xffffffffu, s, 2);
            s += __shfl_xor_sync(0xffffffffu, s, 4);
            int e = e0 + 12 * ty + i;
            if (tx == 0 && e < n_edges) out[e] = s + bias;
        }
    }
}

// ---------------------------------------------------------------------------
extern "C" void kernel_launch(void* const* d_in, const int* in_sizes, int n_in,
                              void* d_out, int out_size) {
    const float* X     = (const float*)d_in[0];
    const int*   pairs = (const int*)d_in[1];
    const float* W1    = (const float*)d_in[2];
    const float* b1    = (const float*)d_in[3];
    const float* W2    = (const float*)d_in[4];
    const float* b2    = (const float*)d_in[5];
    const float* We1   = (const float*)d_in[6];
    const float* be1   = (const float*)d_in[7];
    const float* We2   = (const float*)d_in[8];
    const float* be2   = (const float*)d_in[9];
    float* out = (float*)d_out;

    int n_nodes = in_sizes[0] / 4;
    int n_edges = out_size;

    cudaFuncSetAttribute(node_kernel,
                         cudaFuncAttributeMaxDynamicSharedMemorySize, NODE_SMEM);
    cudaFuncSetAttribute(edge_kernel,
                         cudaFuncAttributeMaxDynamicSharedMemorySize, EDGE_SMEM);

    detect_kernel<<<1, 256>>>(pairs, n_edges);
    decode_kernel<<<(n_edges + 255) / 256, 256>>>(pairs, n_edges);
    node_kernel<<<444, 256, NODE_SMEM>>>(X, W1, b1, W2, b2, We1, be1, n_nodes);
    edge_kernel<<<444, 128, EDGE_SMEM>>>(We1, We2, be2, out, n_edges);
}